// round 3
// baseline (speedup 1.0000x reference)
#include <cuda_runtime.h>

#define N_GRID 64
#define N1 65
#define B_PTS 262144
#define W_FEAT 256
// 64 threads cooperate on one point: each owns 4 features (one float4)
#define THREADS_PER_PT 64
#define BLOCK 256

__global__ __launch_bounds__(BLOCK) void trilinear_kernel(
    const float* __restrict__ x,            // [B, 3]
    const float* __restrict__ grid_value,   // [N1^3, 1]
    const float* __restrict__ grid_feature, // [N1^3, 256]
    float* __restrict__ out,                // [B, 1]
    float* __restrict__ feat)               // [B, 256]
{
    int gid = blockIdx.x * BLOCK + threadIdx.x;
    int pt   = gid >> 6;            // point index
    int lane = gid & 63;            // 0..63 -> float4 slot within feature row
    if (pt >= B_PTS) return;

    // Load point coords (broadcast across the 64-thread group; L1 hit)
    float px = __ldg(&x[pt * 3 + 0]);
    float py = __ldg(&x[pt * 3 + 1]);
    float pz = __ldg(&x[pt * 3 + 2]);

    // rel = (x - min_c) * (N_GRID / SIDE) = (x + 1) * 32
    float rx = (px + 1.0f) * 32.0f;
    float ry = (py + 1.0f) * 32.0f;
    float rz = (pz + 1.0f) * 32.0f;

    bool valid = (rx >= 0.0f) && (rx <= 64.0f) &&
                 (ry >= 0.0f) && (ry <= 64.0f) &&
                 (rz >= 0.0f) && (rz <= 64.0f);

    int ix = min(max((int)floorf(rx), 0), N_GRID - 1);
    int iy = min(max((int)floorf(ry), 0), N_GRID - 1);
    int iz = min(max((int)floorf(rz), 0), N_GRID - 1);

    float tx = rx - (float)ix;
    float ty = ry - (float)iy;
    float tz = rz - (float)iz;
    float sx = 1.0f - tx, sy = 1.0f - ty, sz = 1.0f - tz;

    // 8 corner weights, order: (ox,oy,oz) = 000,001,010,011,100,101,110,111
    float w[8];
    w[0] = sx * sy * sz;
    w[1] = sx * sy * tz;
    w[2] = sx * ty * sz;
    w[3] = sx * ty * tz;
    w[4] = tx * sy * sz;
    w[5] = tx * sy * tz;
    w[6] = tx * ty * sz;
    w[7] = tx * ty * tz;

    int base = (ix * N1 + iy) * N1 + iz;
    int off[8];
    off[0] = base;
    off[1] = base + 1;
    off[2] = base + N1;
    off[3] = base + N1 + 1;
    off[4] = base + N1 * N1;
    off[5] = base + N1 * N1 + 1;
    off[6] = base + N1 * N1 + N1;
    off[7] = base + N1 * N1 + N1 + 1;

    // Gather 8 float4s (independent -> MLP=8) and blend
    float4 acc = make_float4(0.f, 0.f, 0.f, 0.f);
#pragma unroll
    for (int c = 0; c < 8; c++) {
        const float4* row = reinterpret_cast<const float4*>(
            grid_feature + (size_t)off[c] * W_FEAT);
        float4 v = __ldg(row + lane);
        float wc = w[c];
        acc.x = fmaf(wc, v.x, acc.x);
        acc.y = fmaf(wc, v.y, acc.y);
        acc.z = fmaf(wc, v.z, acc.z);
        acc.w = fmaf(wc, v.w, acc.w);
    }

    if (!valid) acc = make_float4(0.f, 0.f, 0.f, 0.f);

    reinterpret_cast<float4*>(feat + (size_t)pt * W_FEAT)[lane] = acc;

    // Lane 0 handles the scalar grid_value gather
    if (lane == 0) {
        float s = 0.0f;
#pragma unroll
        for (int c = 0; c < 8; c++) {
            s = fmaf(w[c], __ldg(&grid_value[off[c]]), s);
        }
        out[pt] = valid ? s : 0.0f;
    }
}

extern "C" void kernel_launch(void* const* d_in, const int* in_sizes, int n_in,
                              void* d_out, int out_size)
{
    const float* x            = (const float*)d_in[0];
    const float* grid_value   = (const float*)d_in[1];
    const float* grid_feature = (const float*)d_in[2];
    float* out  = (float*)d_out;                 // [B, 1] first
    float* feat = (float*)d_out + B_PTS;         // then [B, 256]

    int total_threads = B_PTS * THREADS_PER_PT;  // 16,777,216
    int blocks = total_threads / BLOCK;          // 65,536
    trilinear_kernel<<<blocks, BLOCK>>>(x, grid_value, grid_feature, out, feat);
}

// round 4
// speedup vs baseline: 1.6215x; 1.6215x over previous
#include <cuda_runtime.h>

#define N_GRID 64
#define N1 65
#define B_PTS 262144
#define W_FEAT 256
#define NBINS (N1 * N1 * N1)              // 274625 cells (only 64^3 used, padded)
#define SCAN_BLOCK 256
#define SCAN_ITEMS 8
#define CHUNK (SCAN_BLOCK * SCAN_ITEMS)   // 2048
#define NB_SCAN ((NBINS + CHUNK - 1) / CHUNK)  // 135
#define MAIN_BLOCK 512

// Scratch (device globals: allocation-free per harness rules)
__device__ int    g_hist[NBINS];
__device__ int    g_off[NBINS];
__device__ int    g_bsum[NB_SCAN];
__device__ int    g_cellid[B_PTS];
__device__ float4 g_sorted[B_PTS];        // (px,py,pz, bitcast(pt))

// ---------------------------------------------------------------------------
// K0: zero histogram (must happen every call for graph replay determinism)
__global__ void k_zero_hist() {
    int i = blockIdx.x * blockDim.x + threadIdx.x;
    if (i < NBINS) g_hist[i] = 0;
}

// K1: compute cell id per point + histogram
__global__ void k_cells(const float* __restrict__ x) {
    int pt = blockIdx.x * blockDim.x + threadIdx.x;
    if (pt >= B_PTS) return;
    float rx = (x[3 * pt + 0] + 1.0f) * 32.0f;
    float ry = (x[3 * pt + 1] + 1.0f) * 32.0f;
    float rz = (x[3 * pt + 2] + 1.0f) * 32.0f;
    int ix = min(max((int)floorf(rx), 0), N_GRID - 1);
    int iy = min(max((int)floorf(ry), 0), N_GRID - 1);
    int iz = min(max((int)floorf(rz), 0), N_GRID - 1);
    int cell = (ix * N1 + iy) * N1 + iz;
    g_cellid[pt] = cell;
    atomicAdd(&g_hist[cell], 1);
}

// K2a: per-chunk reduction -> g_bsum[b]
__global__ void k_reduce() {
    int b = blockIdx.x, tid = threadIdx.x;
    int s = 0;
#pragma unroll
    for (int i = 0; i < SCAN_ITEMS; i++) {
        int idx = b * CHUNK + tid * SCAN_ITEMS + i;
        if (idx < NBINS) s += g_hist[idx];
    }
#pragma unroll
    for (int d = 16; d > 0; d >>= 1) s += __shfl_down_sync(0xffffffffu, s, d);
    __shared__ int wsum[SCAN_BLOCK / 32];
    int lane = tid & 31, wid = tid >> 5;
    if (lane == 0) wsum[wid] = s;
    __syncthreads();
    if (wid == 0) {
        s = (lane < SCAN_BLOCK / 32) ? wsum[lane] : 0;
#pragma unroll
        for (int d = 16; d > 0; d >>= 1) s += __shfl_down_sync(0xffffffffu, s, d);
        if (lane == 0) g_bsum[b] = s;
    }
}

// K2b: exclusive scan of the 135 chunk sums (single block, Hillis-Steele)
__global__ void k_scan_bsum() {
    __shared__ int sm[SCAN_BLOCK];
    int tid = threadIdx.x;
    int v = (tid < NB_SCAN) ? g_bsum[tid] : 0;
    sm[tid] = v;
    __syncthreads();
    for (int d = 1; d < SCAN_BLOCK; d <<= 1) {
        int t = (tid >= d) ? sm[tid - d] : 0;
        __syncthreads();
        sm[tid] += t;
        __syncthreads();
    }
    int ex = (tid == 0) ? 0 : sm[tid - 1];
    if (tid < NB_SCAN) g_bsum[tid] = ex;
}

// K2c: per-chunk exclusive scan + chunk offset -> g_off (bin start positions)
__global__ void k_scan_chunks() {
    int b = blockIdx.x, tid = threadIdx.x;
    int base = b * CHUNK + tid * SCAN_ITEMS;
    int v[SCAN_ITEMS];
    int run = 0;
#pragma unroll
    for (int i = 0; i < SCAN_ITEMS; i++) {
        int idx = base + i;
        int h = (idx < NBINS) ? g_hist[idx] : 0;
        v[i] = run;
        run += h;
    }
    // exclusive block scan of per-thread totals
    int lane = tid & 31, wid = tid >> 5;
    int inc = run;
#pragma unroll
    for (int d = 1; d < 32; d <<= 1) {
        int t = __shfl_up_sync(0xffffffffu, inc, d);
        if (lane >= d) inc += t;
    }
    __shared__ int wsum[SCAN_BLOCK / 32];
    __shared__ int woff[SCAN_BLOCK / 32];
    if (lane == 31) wsum[wid] = inc;
    __syncthreads();
    if (tid == 0) {
        int s = 0;
#pragma unroll
        for (int w = 0; w < SCAN_BLOCK / 32; w++) { woff[w] = s; s += wsum[w]; }
    }
    __syncthreads();
    int ex = inc - run + woff[wid] + g_bsum[b];
#pragma unroll
    for (int i = 0; i < SCAN_ITEMS; i++) {
        int idx = base + i;
        if (idx < NBINS) g_off[idx] = ex + v[i];
    }
}

// K3: scatter points into cell-sorted order
__global__ void k_scatter(const float* __restrict__ x) {
    int pt = blockIdx.x * blockDim.x + threadIdx.x;
    if (pt >= B_PTS) return;
    int c = g_cellid[pt];
    int pos = atomicAdd(&g_off[c], 1);
    float4 s;
    s.x = x[3 * pt + 0];
    s.y = x[3 * pt + 1];
    s.z = x[3 * pt + 2];
    s.w = __int_as_float(pt);
    g_sorted[pos] = s;
}

// ---------------------------------------------------------------------------
// K4: trilinear gather over cell-sorted points.
// 64 threads per point; each owns one float4 of the 256-wide feature row.
__global__ __launch_bounds__(MAIN_BLOCK) void k_interp(
    const float* __restrict__ grid_value,   // [N1^3]
    const float* __restrict__ grid_feature, // [N1^3, 256]
    float* __restrict__ out,                // [B]
    float* __restrict__ feat)               // [B, 256]
{
    int gid  = blockIdx.x * MAIN_BLOCK + threadIdx.x;
    int grp  = gid >> 6;       // sorted point index
    int lane = gid & 63;
    if (grp >= B_PTS) return;

    float4 s = g_sorted[grp];  // broadcast within the 64-thread group
    int pt = __float_as_int(s.w);

    float rx = (s.x + 1.0f) * 32.0f;
    float ry = (s.y + 1.0f) * 32.0f;
    float rz = (s.z + 1.0f) * 32.0f;

    bool valid = (rx >= 0.0f) && (rx <= 64.0f) &&
                 (ry >= 0.0f) && (ry <= 64.0f) &&
                 (rz >= 0.0f) && (rz <= 64.0f);

    int ix = min(max((int)floorf(rx), 0), N_GRID - 1);
    int iy = min(max((int)floorf(ry), 0), N_GRID - 1);
    int iz = min(max((int)floorf(rz), 0), N_GRID - 1);

    float tx = rx - (float)ix;
    float ty = ry - (float)iy;
    float tz = rz - (float)iz;
    float ux = 1.0f - tx, uy = 1.0f - ty, uz = 1.0f - tz;

    float w[8];
    w[0] = ux * uy * uz;
    w[1] = ux * uy * tz;
    w[2] = ux * ty * uz;
    w[3] = ux * ty * tz;
    w[4] = tx * uy * uz;
    w[5] = tx * uy * tz;
    w[6] = tx * ty * uz;
    w[7] = tx * ty * tz;

    int base = (ix * N1 + iy) * N1 + iz;
    int off[8];
    off[0] = base;
    off[1] = base + 1;
    off[2] = base + N1;
    off[3] = base + N1 + 1;
    off[4] = base + N1 * N1;
    off[5] = base + N1 * N1 + 1;
    off[6] = base + N1 * N1 + N1;
    off[7] = base + N1 * N1 + N1 + 1;

    float4 acc = make_float4(0.f, 0.f, 0.f, 0.f);
#pragma unroll
    for (int c = 0; c < 8; c++) {
        const float4* row = reinterpret_cast<const float4*>(
            grid_feature + (size_t)off[c] * W_FEAT);
        float4 v = __ldg(row + lane);
        float wc = w[c];
        acc.x = fmaf(wc, v.x, acc.x);
        acc.y = fmaf(wc, v.y, acc.y);
        acc.z = fmaf(wc, v.z, acc.z);
        acc.w = fmaf(wc, v.w, acc.w);
    }

    if (!valid) acc = make_float4(0.f, 0.f, 0.f, 0.f);
    reinterpret_cast<float4*>(feat + (size_t)pt * W_FEAT)[lane] = acc;

    if (lane == 0) {
        float sv = 0.0f;
#pragma unroll
        for (int c = 0; c < 8; c++)
            sv = fmaf(w[c], __ldg(&grid_value[off[c]]), sv);
        out[pt] = valid ? sv : 0.0f;
    }
}

// ---------------------------------------------------------------------------
extern "C" void kernel_launch(void* const* d_in, const int* in_sizes, int n_in,
                              void* d_out, int out_size)
{
    const float* x            = (const float*)d_in[0];
    const float* grid_value   = (const float*)d_in[1];
    const float* grid_feature = (const float*)d_in[2];
    float* out  = (float*)d_out;          // [B,1]
    float* feat = (float*)d_out + B_PTS;  // [B,256]

    k_zero_hist<<<(NBINS + 1023) / 1024, 1024>>>();
    k_cells<<<(B_PTS + 255) / 256, 256>>>(x);
    k_reduce<<<NB_SCAN, SCAN_BLOCK>>>();
    k_scan_bsum<<<1, SCAN_BLOCK>>>();
    k_scan_chunks<<<NB_SCAN, SCAN_BLOCK>>>();
    k_scatter<<<(B_PTS + 255) / 256, 256>>>(x);

    int total_threads = B_PTS * 64;
    k_interp<<<total_threads / MAIN_BLOCK, MAIN_BLOCK>>>(grid_value, grid_feature, out, feat);
}